// round 7
// baseline (speedup 1.0000x reference)
#include <cuda_runtime.h>

#define NN 50000
#define DD 128
#define HH 4
#define CC 16
#define HC 64
#define EE 800000
#define ED 64
#define NEG 0.2f
#define SCAN_B 49   // ceil(50000/1024)
#define XS 18       // padded smem row stride (floats) for transposed x tile

// ---------------- scratch (device globals; no allocs allowed) ----------------
__device__ float g_Wt[DD * HC];          // Wt[d*64+j] = W[j*128+d]
__device__ float g_vt[ED * HH];          // vt[d*4+h] = sum_c att_edge[h,c]*W_edge[h*16+c, d]
__device__ float g_xh[(size_t)NN * HC];
__device__ float g_asrc[NN * HH];
__device__ float g_adst[NN * HH];
__device__ float g_pS[(size_t)EE * HH];  // exp(alpha), CSR-sorted by dst
__device__ int   g_srcS[EE];             // src node, CSR-sorted by dst
__device__ float g_sl[NN * HH];          // per-dst sum of a_edge (self-loop term)
__device__ int   g_deg[NN];
__device__ int   g_pos[EE];
__device__ int   g_off[NN];
__device__ int   g_bsum[64];
__device__ int   g_boff[64];
__device__ int   g_is64;

__device__ __forceinline__ float lrelu(float x) { return x > 0.f ? x : NEG * x; }

__device__ __forceinline__ int ld_idx(const int* __restrict__ ei32, int i, int is64) {
    return is64 ? ei32[2 * (size_t)i] : ei32[i];
}

__device__ __forceinline__ unsigned long long pack2(float a, float b) {
    unsigned long long r;
    asm("mov.b64 %0, {%1, %2};" : "=l"(r) : "r"(__float_as_uint(a)), "r"(__float_as_uint(b)));
    return r;
}
__device__ __forceinline__ void unpack2(unsigned long long v, float& lo, float& hi) {
    unsigned int a, b;
    asm("mov.b64 {%0, %1}, %2;" : "=r"(a), "=r"(b) : "l"(v));
    lo = __uint_as_float(a);
    hi = __uint_as_float(b);
}
__device__ __forceinline__ void fma2(unsigned long long& acc, unsigned long long a,
                                     unsigned long long b) {
    asm("fma.rn.f32x2 %0, %1, %2, %3;" : "=l"(acc) : "l"(a), "l"(b), "l"(acc));
}

// ---------------- init: detect idx width + prep weights + zero accumulators -
__global__ void k_init(const int* __restrict__ ei32,
                       const float* __restrict__ W,
                       const float* __restrict__ W_edge,
                       const float* __restrict__ att_edge) {
    int b = blockIdx.x, t = threadIdx.x;
    if (b == 0) {
        __shared__ int any;
        if (t == 0) any = 0;
        __syncthreads();
        if (ei32[2 * t + 1] != 0) atomicOr(&any, 1);
        __syncthreads();
        if (t == 0) g_is64 = (any == 0) ? 1 : 0;
    } else if (b == 1) {
        for (int idx = t; idx < DD * HC; idx += blockDim.x) {
            int d = idx >> 6, j = idx & 63;
            g_Wt[idx] = W[j * DD + d];
        }
        for (int idx = t; idx < ED * HH; idx += blockDim.x) {
            int h = idx & 3, d = idx >> 2;
            float s = 0.f;
#pragma unroll
            for (int c = 0; c < CC; c++)
                s += att_edge[h * CC + c] * W_edge[(h * CC + c) * ED + d];
            g_vt[idx] = s;
        }
    } else {
        int i = (b - 2) * 256 + t;
        if (i < NN) g_deg[i] = 0;
        if (i < NN * HH) g_sl[i] = 0.f;
    }
}

// ---------------- degree histogram (reads only dst indices) -----------------
__global__ void k_deg(const int* __restrict__ ei32) {
    int e = blockIdx.x * 256 + threadIdx.x;
    int d = ld_idx(ei32, EE + e, g_is64);
    g_pos[e] = atomicAdd(&g_deg[d], 1);
}

// ---------------- exclusive scan of degrees ---------------------------------
__global__ void k_scan1() {
    __shared__ int s[2][1024];
    int t = threadIdx.x;
    int i = blockIdx.x * 1024 + t;
    int v = (i < NN) ? g_deg[i] : 0;
    s[0][t] = v;
    __syncthreads();
    int cur = 0;
    for (int o = 1; o < 1024; o <<= 1) {
        int x = s[cur][t];
        if (t >= o) x += s[cur][t - o];
        s[cur ^ 1][t] = x;
        cur ^= 1;
        __syncthreads();
    }
    int incl = s[cur][t];
    if (i < NN) g_off[i] = incl - v;
    if (t == 1023) g_bsum[blockIdx.x] = incl;
}

__global__ void k_scan2() {
    __shared__ int s[2][64];
    int t = threadIdx.x;
    int v = (t < SCAN_B) ? g_bsum[t] : 0;
    s[0][t] = v;
    __syncthreads();
    int cur = 0;
    for (int o = 1; o < 64; o <<= 1) {
        int x = s[cur][t];
        if (t >= o) x += s[cur][t - o];
        s[cur ^ 1][t] = x;
        cur ^= 1;
        __syncthreads();
    }
    g_boff[t] = s[cur][t] - v;   // exclusive
}

// ---------------- xh = x @ W^T via packed f32x2 FMA; also a_src/a_dst -------
__global__ void k_xh(const float* __restrict__ x,
                     const float* __restrict__ att_src,
                     const float* __restrict__ att_dst) {
    __shared__ float sxT[DD * XS];
    int n0 = blockIdx.x * 16;
    int t = threadIdx.x;

    const float4* xv = (const float4*)(x + (size_t)n0 * DD);
#pragma unroll
    for (int i = 0; i < 8; i++) {
        int f = t + i * 64;
        int node = f >> 5;
        int d4 = f & 31;
        float4 v = xv[node * 32 + d4];
        int d = d4 * 4;
        sxT[(d + 0) * XS + node] = v.x;
        sxT[(d + 1) * XS + node] = v.y;
        sxT[(d + 2) * XS + node] = v.z;
        sxT[(d + 3) * XS + node] = v.w;
    }
    __syncthreads();

    unsigned long long acc2[8];
#pragma unroll
    for (int p = 0; p < 8; p++) acc2[p] = 0ull;

#pragma unroll 4
    for (int d = 0; d < DD; d++) {
        float w = __ldg(&g_Wt[d * HC + t]);
        unsigned long long wp = pack2(w, w);
        const unsigned long long* row = (const unsigned long long*)(sxT + d * XS);
#pragma unroll
        for (int p = 0; p < 8; p++) fma2(acc2[p], row[p], wp);
    }

    float xhv[16];
#pragma unroll
    for (int p = 0; p < 8; p++) {
        unpack2(acc2[p], xhv[2 * p], xhv[2 * p + 1]);
        g_xh[(size_t)(n0 + 2 * p) * HC + t] = xhv[2 * p];
        g_xh[(size_t)(n0 + 2 * p + 1) * HC + t] = xhv[2 * p + 1];
    }

    float as = att_src[t], ad = att_dst[t];
#pragma unroll
    for (int k = 0; k < 16; k++) {
        float vs = xhv[k] * as;
        float vd = xhv[k] * ad;
#pragma unroll
        for (int o = 8; o; o >>= 1) {
            vs += __shfl_down_sync(0xffffffffu, vs, o, 16);
            vd += __shfl_down_sync(0xffffffffu, vd, o, 16);
        }
        if ((t & 15) == 0) {
            g_asrc[(n0 + k) * HH + (t >> 4)] = vs;
            g_adst[(n0 + k) * HH + (t >> 4)] = vd;
        }
    }
}

// ---------------- per-edge: a_edge dot + exp(alpha), written into CSR -------
__global__ void k_edgeA(const float* __restrict__ edge_attr,
                        const int* __restrict__ ei32) {
    __shared__ float svt[ED * HH];
    int tid = threadIdx.x;
    svt[tid] = g_vt[tid];
    __syncthreads();

    int g = tid >> 4, t = tid & 15;
    int e = blockIdx.x * 16 + g;

    float4 a = ((const float4*)(edge_attr + (size_t)e * ED))[t];
    const float4* vt4 = (const float4*)svt;
    float4 w0 = vt4[4 * t + 0], w1 = vt4[4 * t + 1];
    float4 w2 = vt4[4 * t + 2], w3 = vt4[4 * t + 3];
    float r0 = a.x * w0.x + a.y * w1.x + a.z * w2.x + a.w * w3.x;
    float r1 = a.x * w0.y + a.y * w1.y + a.z * w2.y + a.w * w3.y;
    float r2 = a.x * w0.z + a.y * w1.z + a.z * w2.z + a.w * w3.z;
    float r3 = a.x * w0.w + a.y * w1.w + a.z * w2.w + a.w * w3.w;
#pragma unroll
    for (int o = 8; o; o >>= 1) {
        r0 += __shfl_down_sync(0xffffffffu, r0, o, 16);
        r1 += __shfl_down_sync(0xffffffffu, r1, o, 16);
        r2 += __shfl_down_sync(0xffffffffu, r2, o, 16);
        r3 += __shfl_down_sync(0xffffffffu, r3, o, 16);
    }
    if (t == 0) {
        int is64 = g_is64;
        int s = ld_idx(ei32, e, is64);
        int d = ld_idx(ei32, EE + e, is64);
        float4 as4 = *(const float4*)(g_asrc + s * 4);
        float4 ad4 = *(const float4*)(g_adst + d * 4);
        float4 p = make_float4(__expf(lrelu(as4.x + ad4.x + r0)),
                               __expf(lrelu(as4.y + ad4.y + r1)),
                               __expf(lrelu(as4.z + ad4.z + r2)),
                               __expf(lrelu(as4.w + ad4.w + r3)));
        int slot = g_off[d] + g_boff[d >> 10] + g_pos[e];
        g_srcS[slot] = s;
        *(float4*)(g_pS + (size_t)slot * 4) = p;
        atomicAdd(&g_sl[d * 4 + 0], r0);
        atomicAdd(&g_sl[d * 4 + 1], r1);
        atomicAdd(&g_sl[d * 4 + 2], r2);
        atomicAdd(&g_sl[d * 4 + 3], r3);
    }
}

// ---------------- 2 warps per destination: weighted aggregate ---------------
// exp() pre-computed in k_edgeA; loop body is pure ld+fma (no MUFU).
__global__ void k_dst(const float* __restrict__ bias,
                      float* __restrict__ out) {
    int w = threadIdx.x >> 5, lane = threadIdx.x & 31;
    int n = blockIdx.x * 4 + (w >> 1);
    int half = w & 1;
    int ch = half * 32 + lane;
    int head = ch >> 4;
    int start = g_off[n] + g_boff[n >> 10];
    int deg = g_deg[n];

    // self-loop p (loop_attr dot folded in via linearity of the a_edge dot)
    float idg = 1.f / (float)(deg > 1 ? deg : 1);
    float4 sl = *(const float4*)(g_sl + n * 4);
    float4 as4 = *(const float4*)(g_asrc + n * 4);
    float4 ad4 = *(const float4*)(g_adst + n * 4);
    float l0 = lrelu(as4.x + ad4.x + sl.x * idg);
    float l1 = lrelu(as4.y + ad4.y + sl.y * idg);
    float l2 = lrelu(as4.z + ad4.z + sl.z * idg);
    float l3 = lrelu(as4.w + ad4.w + sl.w * idg);
    float lv = (head == 0) ? l0 : (head == 1) ? l1 : (head == 2) ? l2 : l3;

    float pSelf = __expf(lv);
    float den = pSelf;
    float acc = g_xh[(size_t)n * HC + ch] * pSelf;

#pragma unroll 4
    for (int i = 0; i < deg; i++) {
        int slot = start + i;
        int s = g_srcS[slot];
        float p = g_pS[(size_t)slot * 4 + head];
        den += p;
        acc += g_xh[(size_t)s * HC + ch] * p;
    }
    out[(size_t)n * HC + ch] = bias[ch] + acc / (den + 1e-16f);
}

// ---------------- launch ----------------------------------------------------
extern "C" void kernel_launch(void* const* d_in, const int* in_sizes, int n_in,
                              void* d_out, int out_size) {
    const float* x         = (const float*)d_in[0];
    const int*   ei32      = (const int*)d_in[1];
    const float* edge_attr = (const float*)d_in[2];
    const float* W         = (const float*)d_in[3];
    const float* W_edge    = (const float*)d_in[4];
    const float* att_src   = (const float*)d_in[5];
    const float* att_dst   = (const float*)d_in[6];
    const float* att_edge  = (const float*)d_in[7];
    const float* bias      = (const float*)d_in[8];
    float* out = (float*)d_out;

    k_init<<<2 + (NN * HH + 255) / 256, 256>>>(ei32, W, W_edge, att_edge);
    k_deg<<<EE / 256, 256>>>(ei32);
    k_scan1<<<SCAN_B, 1024>>>();
    k_scan2<<<1, 64>>>();
    k_xh<<<NN / 16, 64>>>(x, att_src, att_dst);
    k_edgeA<<<EE / 16, 256>>>(edge_attr, ei32);
    k_dst<<<NN / 4, 256>>>(bias, out);
}